// round 14
// baseline (speedup 1.0000x reference)
#include <cuda_runtime.h>
#include <cuda_fp16.h>
#include <math.h>
#include <stdint.h>

#define D_MODEL 1024
#define NHEAD   16
#define HEAD_DIM 64
#define BATCH   2
#define SEQ     2048
#define M_TOT   (BATCH*SEQ)          // 4096

// fp16 scratch: Q hi/lo (pre-scaled by 0.125); K, V hi only; data hi/lo; W hi
__device__ __half g_Qh[BATCH*NHEAD*SEQ*HEAD_DIM];
__device__ __half g_Ql[BATCH*NHEAD*SEQ*HEAD_DIM];
__device__ __half g_Kh[BATCH*NHEAD*SEQ*HEAD_DIM];
__device__ __half g_Vh[BATCH*NHEAD*SEQ*HEAD_DIM];
__device__ __half g_Dh[M_TOT*D_MODEL];
__device__ __half g_Dl[M_TOT*D_MODEL];
__device__ __half g_Wh[3*D_MODEL*D_MODEL];

#define LOG2_10K 13.287712379549449f

// ===========================================================================
// helpers
// ===========================================================================
__device__ __forceinline__ uint32_t smem_u32(const void* p) {
    uint32_t a;
    asm("{ .reg .u64 t; cvta.to.shared.u64 t, %1; cvt.u32.u64 %0, t; }"
        : "=r"(a) : "l"(p));
    return a;
}
__device__ __forceinline__ void ldsm_x4(uint32_t* r, uint32_t addr) {
    asm volatile("ldmatrix.sync.aligned.m8n8.x4.shared.b16 {%0,%1,%2,%3}, [%4];"
        : "=r"(r[0]), "=r"(r[1]), "=r"(r[2]), "=r"(r[3]) : "r"(addr));
}
__device__ __forceinline__ void ldsm_x4t(uint32_t* r, uint32_t addr) {
    asm volatile("ldmatrix.sync.aligned.m8n8.x4.trans.shared.b16 {%0,%1,%2,%3}, [%4];"
        : "=r"(r[0]), "=r"(r[1]), "=r"(r[2]), "=r"(r[3]) : "r"(addr));
}
__device__ __forceinline__ void mma16816(float* c, const uint32_t* a, const uint32_t* b) {
    asm volatile("mma.sync.aligned.m16n8k16.row.col.f32.f16.f16.f32 "
        "{%0,%1,%2,%3}, {%4,%5,%6,%7}, {%8,%9}, {%0,%1,%2,%3};"
        : "+f"(c[0]), "+f"(c[1]), "+f"(c[2]), "+f"(c[3])
        : "r"(a[0]), "r"(a[1]), "r"(a[2]), "r"(a[3]), "r"(b[0]), "r"(b[1]));
}
__device__ __forceinline__ void cp16(uint32_t saddr, const void* g) {
    asm volatile("cp.async.cg.shared.global [%0], [%1], 16;" :: "r"(saddr), "l"(g));
}
#define CP_COMMIT() asm volatile("cp.async.commit_group;" ::: "memory")
#define CP_WAIT0()  asm volatile("cp.async.wait_group 0;" ::: "memory")
#define CP_WAIT1()  asm volatile("cp.async.wait_group 1;" ::: "memory")

union H2U { __half2 h2; unsigned u; };
__device__ __forceinline__ unsigned packhf(float x, float y) {
    H2U u; u.h2 = __floats2half2_rn(x, y); return u.u;
}
__device__ __forceinline__ float2 unpackhf(unsigned v) {
    H2U u; u.u = v;
    return __half22float2(u.h2);
}
__device__ __forceinline__ void split4h(float4 v, uint2& hi, uint2& lo) {
    H2U h0, h1, l0, l1;
    h0.h2 = __floats2half2_rn(v.x, v.y);
    h1.h2 = __floats2half2_rn(v.z, v.w);
    float2 f0 = __half22float2(h0.h2);
    float2 f1 = __half22float2(h1.h2);
    l0.h2 = __floats2half2_rn(v.x - f0.x, v.y - f0.y);
    l1.h2 = __floats2half2_rn(v.z - f1.x, v.w - f1.y);
    hi = make_uint2(h0.u, h1.u);
    lo = make_uint2(l0.u, l1.u);
}

// ===========================================================================
// Split kernels
// ===========================================================================
__global__ __launch_bounds__(256) void dsplit_kernel(const float* __restrict__ src) {
    int idx = blockIdx.x * 256 + threadIdx.x;
    float4 v = *(const float4*)(src + (size_t)idx * 4);
    uint2 hi, lo;
    split4h(v, hi, lo);
    *(uint2*)(g_Dh + (size_t)idx * 4) = hi;
    *(uint2*)(g_Dl + (size_t)idx * 4) = lo;
}

// W transpose + fp16 convert (hi only)
__global__ __launch_bounds__(256) void wsplit_kernel(
    const float* __restrict__ Wq, const float* __restrict__ Wk,
    const float* __restrict__ Wv)
{
    __shared__ __half th[32][40];
    const int mat = blockIdx.z;
    const float* __restrict__ W = (mat == 0) ? Wq : ((mat == 1) ? Wk : Wv);
    const int tid = threadIdx.x;
    const int k0 = blockIdx.x * 32;
    const int n0 = blockIdx.y * 32;
    {
        int r = tid >> 3, c4 = (tid & 7) * 4;
        float4 v = *(const float4*)(W + (size_t)(k0 + r) * D_MODEL + n0 + c4);
        H2U a, b;
        a.h2 = __floats2half2_rn(v.x, v.y);
        b.h2 = __floats2half2_rn(v.z, v.w);
        *(uint2*)&th[r][c4] = make_uint2(a.u, b.u);
    }
    __syncthreads();
    {
        int r = tid >> 3, c4 = (tid & 7) * 4;
        __half hh[4];
        #pragma unroll
        for (int j = 0; j < 4; ++j) hh[j] = th[c4 + j][r];
        size_t o = ((size_t)mat << 20) + (size_t)(n0 + r) * D_MODEL + k0 + c4;
        *(uint2*)(g_Wh + o) = *(uint2*)hh;
    }
}

// ===========================================================================
// QKV GEMM: fp16 HMMA 2-pass ((Dh+Dl)·Wh), 128x128 tile, BK=32, dbl-buffer,
// 2 CTAs/SM. Q output pre-scaled by 0.125 (softmax scale folded in).
// ===========================================================================
#define ASTR 40
#define QT_BYTES (128 * ASTR * 2)      // 10240 per tile
#define QBUF_BYTES (3 * QT_BYTES)      // AH, AL, BH
#define QKV_SMEM (2 * QBUF_BYTES)      // 61440

__global__ __launch_bounds__(256, 2) void qkv_mma_kernel(
    const float* __restrict__ temporal,
    const float* __restrict__ bq, const float* __restrict__ bk,
    const float* __restrict__ bv)
{
    extern __shared__ char qsm[];
    const uint32_t base = smem_u32(qsm);

    const int mat = blockIdx.z;
    const float* __restrict__ bias = (mat == 0) ? bq : ((mat == 1) ? bk : bv);
    __half* __restrict__ outH = (mat == 0) ? g_Qh : ((mat == 1) ? g_Kh : g_Vh);
    const __half* __restrict__ Wh = g_Wh + ((size_t)mat << 20);

    const int tid = threadIdx.x;
    const int lane = tid & 31;
    const int wid = tid >> 5;
    const int wm = wid & 1;
    const int wn = wid >> 1;
    const int m0 = blockIdx.x * 128;
    const int n0 = blockIdx.y * 128;

    const int lrow = tid >> 2;
    const int lc8  = (tid & 3) * 8;

    auto prefetch = [&](int kk, int buf) {
        uint32_t bb = base + buf * QBUF_BYTES;
        #pragma unroll
        for (int it = 0; it < 2; ++it) {
            int row = lrow + it * 64;
            uint32_t so = (uint32_t)(row * ASTR + lc8) * 2;
            size_t ga = (size_t)(m0 + row) * D_MODEL + kk + lc8;
            size_t gb = (size_t)(n0 + row) * D_MODEL + kk + lc8;
            cp16(bb + so,                 g_Dh + ga);
            cp16(bb + QT_BYTES + so,      g_Dl + ga);
            cp16(bb + 2 * QT_BYTES + so,  Wh + gb);
        }
    };

    float acc[4][4][4];
    #pragma unroll
    for (int i = 0; i < 4; ++i)
        #pragma unroll
        for (int j = 0; j < 4; ++j)
            #pragma unroll
            for (int e = 0; e < 4; ++e) acc[i][j][e] = 0.0f;

    prefetch(0, 0);
    CP_COMMIT();

    for (int c = 0; c < 32; ++c) {
        __syncthreads();
        if (c + 1 < 32) {
            prefetch((c + 1) * 32, (c + 1) & 1);
            CP_COMMIT();
            CP_WAIT1();
        } else {
            CP_WAIT0();
        }
        __syncthreads();

        const uint32_t bb = base + (c & 1) * QBUF_BYTES;
        const uint32_t bAh = bb;
        const uint32_t bAl = bb + QT_BYTES;
        const uint32_t bBh = bb + 2 * QT_BYTES;

        #pragma unroll
        for (int ks = 0; ks < 2; ++ks) {
            const int ko = ks * 16;
            uint32_t Ah[4][4], Al[4][4], Bh[2][4];
            const uint32_t aoff = (uint32_t)((wm * 64 + (lane & 15)) * ASTR
                                             + ko + ((lane >> 4) << 3)) * 2;
            #pragma unroll
            for (int ma = 0; ma < 4; ++ma) {
                ldsm_x4(Ah[ma], bAh + aoff + ma * 16 * ASTR * 2);
                ldsm_x4(Al[ma], bAl + aoff + ma * 16 * ASTR * 2);
            }
            {
                const int m = lane >> 3;
                #pragma unroll
                for (int nbp = 0; nbp < 2; ++nbp) {
                    int rr = wn * 32 + nbp * 16 + ((m >> 1) << 3) + (lane & 7);
                    int cc = ko + ((m & 1) << 3);
                    uint32_t off = (uint32_t)(rr * ASTR + cc) * 2;
                    ldsm_x4(Bh[nbp], bBh + off);
                }
            }
            #pragma unroll
            for (int ma = 0; ma < 4; ++ma)
                #pragma unroll
                for (int nbp = 0; nbp < 2; ++nbp) {
                    mma16816(acc[ma][2*nbp+0], Ah[ma], Bh[nbp] + 0);
                    mma16816(acc[ma][2*nbp+1], Ah[ma], Bh[nbp] + 2);
                }
            #pragma unroll
            for (int ma = 0; ma < 4; ++ma)
                #pragma unroll
                for (int nbp = 0; nbp < 2; ++nbp) {
                    mma16816(acc[ma][2*nbp+0], Al[ma], Bh[nbp] + 0);
                    mma16816(acc[ma][2*nbp+1], Al[ma], Bh[nbp] + 2);
                }
        }
    }

    // Epilogue: bias + RoPE; Q additionally scaled by 0.125, split hi/lo.
    #pragma unroll
    for (int ma = 0; ma < 4; ++ma) {
        const int r0 = m0 + wm * 64 + ma * 16 + (lane >> 2);
        #pragma unroll
        for (int rg = 0; rg < 2; ++rg) {
            const int r = r0 + rg * 8;
            const int bb = r >> 11;
            const int ll = r & (SEQ - 1);
            float t = 0.0f;
            if (mat < 2) t = temporal[r];
            #pragma unroll
            for (int nb = 0; nb < 4; ++nb) {
                const int n = n0 + wn * 32 + nb * 8 + (lane & 3) * 2;
                const int hh = n >> 6;
                const int s = n & 63;
                float x0 = acc[ma][nb][rg * 2 + 0] + bias[n];
                float x1 = acc[ma][nb][rg * 2 + 1] + bias[n + 1];
                float2 v;
                if (mat < 2) {
                    float f = exp2f(-(float)s * (LOG2_10K / (float)HEAD_DIM));
                    float sn, cs;
                    sincosf(t * f, &sn, &cs);
                    v.x = x0 * cs - x1 * sn;
                    v.y = x1 * cs + x0 * sn;
                } else {
                    v.x = x0; v.y = x1;
                }
                if (mat == 0) { v.x *= 0.125f; v.y *= 0.125f; }
                unsigned uh = packhf(v.x, v.y);
                size_t o = (((size_t)(bb * NHEAD + hh)) * SEQ + ll) * HEAD_DIM + s;
                *(unsigned*)(outH + o) = uh;
                if (mat == 0) {
                    float2 hv = unpackhf(uh);
                    *(unsigned*)(g_Ql + o) = packhf(v.x - hv.x, v.y - hv.y);
                }
            }
        }
    }
}

// ===========================================================================
// Flash attention: fp16 HMMA 2-pass. Q block 64 (hi/lo, pre-scaled), K/V
// fp16-hi only, KV tile 64 double-buffered, mask inline, 4 CTAs/SM.
// S = (Qh+Ql)·Kh ; O += (Ph+Pl)·Vh
// ===========================================================================
#define FSTR 72
#define HT_BYTES (64 * FSTR * 2)           // 9216 per 64-row fp16 tile
#define KVBUF_BYTES (2 * HT_BYTES)         // KH, VH = 18432
#define O_QH 0
#define O_QL HT_BYTES
#define O_KV (2 * HT_BYTES)
#define AT_SMEM (2 * HT_BYTES + 2 * KVBUF_BYTES)   // 55296

__global__ __launch_bounds__(128, 4) void attn_mma_kernel(
    const float* __restrict__ mask, float* __restrict__ out)
{
    extern __shared__ char smc[];
    const uint32_t base = smem_u32(smc);

    const int tid = threadIdx.x;
    const int lane = tid & 31;
    const int wid = tid >> 5;          // 0..3
    const int q0 = blockIdx.x * 64;
    const int hh = blockIdx.y;
    const int bb = blockIdx.z;

    const size_t hb = ((size_t)(bb * NHEAD + hh)) * SEQ * HEAD_DIM;

    // Q prefetch: 64 rows x 64 cols hi/lo
    {
        #pragma unroll
        for (int it = 0; it < 4; ++it) {
            int idx = tid + it * 128;
            int row = idx >> 3;
            int c8  = (idx & 7) * 8;
            uint32_t so = (uint32_t)(row * FSTR + c8) * 2;
            size_t g = hb + (size_t)(q0 + row) * HEAD_DIM + c8;
            cp16(base + O_QH + so, g_Qh + g);
            cp16(base + O_QL + so, g_Ql + g);
        }
    }

    auto prefetch_kv = [&](int c, int buf) {
        uint32_t bbse = base + O_KV + buf * KVBUF_BYTES;
        #pragma unroll
        for (int it = 0; it < 4; ++it) {
            int idx = tid + it * 128;
            int row = idx >> 3;
            int c8  = (idx & 7) * 8;
            uint32_t so = (uint32_t)(row * FSTR + c8) * 2;
            size_t g = hb + (size_t)(c * 64 + row) * HEAD_DIM + c8;
            cp16(bbse + so,            g_Kh + g);
            cp16(bbse + HT_BYTES + so, g_Vh + g);
        }
    };
    prefetch_kv(0, 0);
    CP_COMMIT();

    float O[8][4];
    #pragma unroll
    for (int i = 0; i < 8; ++i)
        #pragma unroll
        for (int e = 0; e < 4; ++e) O[i][e] = 0.0f;
    float mrow[2] = {-INFINITY, -INFINITY};
    float lrow_[2] = {0.0f, 0.0f};

    const int r0 = lane >> 2;
    const int qr0 = q0 + wid * 16 + r0;
    const int cq = (lane & 3) * 2;
    const int m = lane >> 3;

    const int NIT = SEQ / 64;
    for (int c = 0; c < NIT; ++c) {
        __syncthreads();
        if (c + 1 < NIT) {
            prefetch_kv(c + 1, (c + 1) & 1);
            CP_COMMIT();
            CP_WAIT1();
        } else {
            CP_WAIT0();
        }
        __syncthreads();

        const uint32_t bufb = base + O_KV + (c & 1) * KVBUF_BYTES;
        const uint32_t bKH = bufb;
        const uint32_t bVH = bufb + HT_BYTES;
        const int k0 = c * 64;

        // --- S = (Qh+Ql).Kh^T (2-pass), warp strip m16 x n64 ---
        float acc[8][4];
        #pragma unroll
        for (int i = 0; i < 8; ++i)
            #pragma unroll
            for (int e = 0; e < 4; ++e) acc[i][e] = 0.0f;

        #pragma unroll
        for (int ks = 0; ks < 4; ++ks) {
            uint32_t Ah[4], Al[4];
            const uint32_t aoff = (uint32_t)((wid * 16 + (lane & 15)) * FSTR
                                             + ks * 16 + ((lane >> 4) << 3)) * 2;
            ldsm_x4(Ah, base + O_QH + aoff);
            ldsm_x4(Al, base + O_QL + aoff);
            uint32_t Bh[4][4];
            #pragma unroll
            for (int nbp = 0; nbp < 4; ++nbp) {
                int rr = nbp * 16 + ((m >> 1) << 3) + (lane & 7);
                int cc = ks * 16 + ((m & 1) << 3);
                uint32_t off = (uint32_t)(rr * FSTR + cc) * 2;
                ldsm_x4(Bh[nbp], bKH + off);
            }
            #pragma unroll
            for (int nbp = 0; nbp < 4; ++nbp) {
                mma16816(acc[2*nbp+0], Ah, Bh[nbp] + 0);
                mma16816(acc[2*nbp+1], Ah, Bh[nbp] + 2);
            }
            #pragma unroll
            for (int nbp = 0; nbp < 4; ++nbp) {
                mma16816(acc[2*nbp+0], Al, Bh[nbp] + 0);
                mma16816(acc[2*nbp+1], Al, Bh[nbp] + 2);
            }
        }

        // --- online softmax (warp-local, quad shuffles), mask inline ---
        #pragma unroll
        for (int rg = 0; rg < 2; ++rg) {
            const float* mp = mask + (size_t)(qr0 + rg * 8) * SEQ + k0;
            float tm = -INFINITY;
            #pragma unroll
            for (int nb = 0; nb < 8; ++nb) {
                float2 mv = *(const float2*)(mp + nb * 8 + cq);
                float x0 = acc[nb][rg * 2 + 0] + mv.x;
                float x1 = acc[nb][rg * 2 + 1] + mv.y;
                acc[nb][rg * 2 + 0] = x0;
                acc[nb][rg * 2 + 1] = x1;
                tm = fmaxf(tm, fmaxf(x0, x1));
            }
            tm = fmaxf(tm, __shfl_xor_sync(0xffffffffu, tm, 1));
            tm = fmaxf(tm, __shfl_xor_sync(0xffffffffu, tm, 2));
            float mn = fmaxf(mrow[rg], tm);
            float corr = __expf(mrow[rg] - mn);
            float rs = 0.0f;
            #pragma unroll
            for (int nb = 0; nb < 8; ++nb) {
                float p0 = __expf(acc[nb][rg * 2 + 0] - mn);
                float p1 = __expf(acc[nb][rg * 2 + 1] - mn);
                acc[nb][rg * 2 + 0] = p0;
                acc[nb][rg * 2 + 1] = p1;
                rs += p0 + p1;
            }
            rs += __shfl_xor_sync(0xffffffffu, rs, 1);
            rs += __shfl_xor_sync(0xffffffffu, rs, 2);
            lrow_[rg] = lrow_[rg] * corr + rs;
            mrow[rg] = mn;
            #pragma unroll
            for (int nb = 0; nb < 8; ++nb) {
                O[nb][rg * 2 + 0] *= corr;
                O[nb][rg * 2 + 1] *= corr;
            }
        }

        // --- O += (Ph+Pl).Vh (2-pass), P split from registers ---
        #pragma unroll
        for (int ks = 0; ks < 4; ++ks) {
            uint32_t ph[4], pl[4];
            #pragma unroll
            for (int half = 0; half < 2; ++half) {
                const float* a0 = acc[2 * ks + half];
                unsigned h01 = packhf(a0[0], a0[1]);
                unsigned h23 = packhf(a0[2], a0[3]);
                float2 f01 = unpackhf(h01);
                float2 f23 = unpackhf(h23);
                unsigned l01 = packhf(a0[0] - f01.x, a0[1] - f01.y);
                unsigned l23 = packhf(a0[2] - f23.x, a0[3] - f23.y);
                ph[half * 2 + 0] = h01; ph[half * 2 + 1] = h23;
                pl[half * 2 + 0] = l01; pl[half * 2 + 1] = l23;
            }
            uint32_t Vh[4][4];
            #pragma unroll
            for (int nbp = 0; nbp < 4; ++nbp) {
                int rr = ks * 16 + ((m & 1) << 3) + (lane & 7);
                int cc = nbp * 16 + ((m >> 1) << 3);
                uint32_t off = (uint32_t)(rr * FSTR + cc) * 2;
                ldsm_x4t(Vh[nbp], bVH + off);
            }
            #pragma unroll
            for (int nbp = 0; nbp < 4; ++nbp) {
                mma16816(O[2*nbp+0], ph, Vh[nbp] + 0);
                mma16816(O[2*nbp+1], ph, Vh[nbp] + 2);
            }
            #pragma unroll
            for (int nbp = 0; nbp < 4; ++nbp) {
                mma16816(O[2*nbp+0], pl, Vh[nbp] + 0);
                mma16816(O[2*nbp+1], pl, Vh[nbp] + 2);
            }
        }
    }

    // Epilogue
    float inv0 = 1.0f / lrow_[0];
    float inv1 = 1.0f / lrow_[1];
    #pragma unroll
    for (int rg = 0; rg < 2; ++rg) {
        float inv = rg ? inv1 : inv0;
        size_t ob = (size_t)(bb * SEQ + qr0 + rg * 8) * D_MODEL + hh * HEAD_DIM;
        #pragma unroll
        for (int nb = 0; nb < 8; ++nb) {
            float2 v = make_float2(O[nb][rg * 2 + 0] * inv, O[nb][rg * 2 + 1] * inv);
            *(float2*)(out + ob + nb * 8 + cq) = v;
        }
    }
}

// ---------------------------------------------------------------------------
// Launch. inputs: 0=data 1=temporal 2=mask 3=Wq 4=bq 5=Wk 6=bk 7=Wv 8=bv
// ---------------------------------------------------------------------------
extern "C" void kernel_launch(void* const* d_in, const int* in_sizes, int n_in,
                              void* d_out, int out_size)
{
    const float* data     = (const float*)d_in[0];
    const float* temporal = (const float*)d_in[1];
    const float* mask     = (const float*)d_in[2];
    const float* Wq = (const float*)d_in[3];
    const float* bq = (const float*)d_in[4];
    const float* Wk = (const float*)d_in[5];
    const float* bk = (const float*)d_in[6];
    const float* Wv = (const float*)d_in[7];
    const float* bv = (const float*)d_in[8];
    float* out = (float*)d_out;

    cudaFuncSetAttribute(qkv_mma_kernel,
                         cudaFuncAttributeMaxDynamicSharedMemorySize, QKV_SMEM);
    cudaFuncSetAttribute(attn_mma_kernel,
                         cudaFuncAttributeMaxDynamicSharedMemorySize, AT_SMEM);

    dsplit_kernel<<<(M_TOT * D_MODEL / 4) / 256, 256>>>(data);
    dim3 gw(D_MODEL / 32, D_MODEL / 32, 3);
    wsplit_kernel<<<gw, 256>>>(Wq, Wk, Wv);

    dim3 g1(M_TOT / 128, D_MODEL / 128, 3);
    qkv_mma_kernel<<<g1, 256, QKV_SMEM>>>(temporal, bq, bk, bv);

    dim3 g2(SEQ / 64, NHEAD, BATCH);
    attn_mma_kernel<<<g2, 128, AT_SMEM>>>(mask, out);
}

// round 17
// speedup vs baseline: 1.1209x; 1.1209x over previous
#include <cuda_runtime.h>
#include <cuda_fp16.h>
#include <math.h>
#include <stdint.h>

#define D_MODEL 1024
#define NHEAD   16
#define HEAD_DIM 64
#define BATCH   2
#define SEQ     2048
#define M_TOT   (BATCH*SEQ)          // 4096

// fp16 scratch: Q (pre-scaled by 0.125), K, V hi; data hi/lo; W hi
__device__ __half g_Qh[BATCH*NHEAD*SEQ*HEAD_DIM];
__device__ __half g_Kh[BATCH*NHEAD*SEQ*HEAD_DIM];
__device__ __half g_Vh[BATCH*NHEAD*SEQ*HEAD_DIM];
__device__ __half g_Dh[M_TOT*D_MODEL];
__device__ __half g_Dl[M_TOT*D_MODEL];
__device__ __half g_Wh[3*D_MODEL*D_MODEL];

#define LOG2_10K 13.287712379549449f

// ===========================================================================
// helpers
// ===========================================================================
__device__ __forceinline__ uint32_t smem_u32(const void* p) {
    uint32_t a;
    asm("{ .reg .u64 t; cvta.to.shared.u64 t, %1; cvt.u32.u64 %0, t; }"
        : "=r"(a) : "l"(p));
    return a;
}
__device__ __forceinline__ void ldsm_x4(uint32_t* r, uint32_t addr) {
    asm volatile("ldmatrix.sync.aligned.m8n8.x4.shared.b16 {%0,%1,%2,%3}, [%4];"
        : "=r"(r[0]), "=r"(r[1]), "=r"(r[2]), "=r"(r[3]) : "r"(addr));
}
__device__ __forceinline__ void ldsm_x4t(uint32_t* r, uint32_t addr) {
    asm volatile("ldmatrix.sync.aligned.m8n8.x4.trans.shared.b16 {%0,%1,%2,%3}, [%4];"
        : "=r"(r[0]), "=r"(r[1]), "=r"(r[2]), "=r"(r[3]) : "r"(addr));
}
__device__ __forceinline__ void mma16816(float* c, const uint32_t* a, const uint32_t* b) {
    asm volatile("mma.sync.aligned.m16n8k16.row.col.f32.f16.f16.f32 "
        "{%0,%1,%2,%3}, {%4,%5,%6,%7}, {%8,%9}, {%0,%1,%2,%3};"
        : "+f"(c[0]), "+f"(c[1]), "+f"(c[2]), "+f"(c[3])
        : "r"(a[0]), "r"(a[1]), "r"(a[2]), "r"(a[3]), "r"(b[0]), "r"(b[1]));
}
__device__ __forceinline__ void cp16(uint32_t saddr, const void* g) {
    asm volatile("cp.async.cg.shared.global [%0], [%1], 16;" :: "r"(saddr), "l"(g));
}
#define CP_COMMIT() asm volatile("cp.async.commit_group;" ::: "memory")
#define CP_WAIT0()  asm volatile("cp.async.wait_group 0;" ::: "memory")
#define CP_WAIT1()  asm volatile("cp.async.wait_group 1;" ::: "memory")

union H2U { __half2 h2; unsigned u; };
__device__ __forceinline__ unsigned packhf(float x, float y) {
    H2U u; u.h2 = __floats2half2_rn(x, y); return u.u;
}
__device__ __forceinline__ void split4h(float4 v, uint2& hi, uint2& lo) {
    H2U h0, h1, l0, l1;
    h0.h2 = __floats2half2_rn(v.x, v.y);
    h1.h2 = __floats2half2_rn(v.z, v.w);
    float2 f0 = __half22float2(h0.h2);
    float2 f1 = __half22float2(h1.h2);
    l0.h2 = __floats2half2_rn(v.x - f0.x, v.y - f0.y);
    l1.h2 = __floats2half2_rn(v.z - f1.x, v.w - f1.y);
    hi = make_uint2(h0.u, h1.u);
    lo = make_uint2(l0.u, l1.u);
}

// ===========================================================================
// Split kernels
// ===========================================================================
__global__ __launch_bounds__(256) void dsplit_kernel(const float* __restrict__ src) {
    int idx = blockIdx.x * 256 + threadIdx.x;
    float4 v = *(const float4*)(src + (size_t)idx * 4);
    uint2 hi, lo;
    split4h(v, hi, lo);
    *(uint2*)(g_Dh + (size_t)idx * 4) = hi;
    *(uint2*)(g_Dl + (size_t)idx * 4) = lo;
}

// W transpose + fp16 convert (hi only)
__global__ __launch_bounds__(256) void wsplit_kernel(
    const float* __restrict__ Wq, const float* __restrict__ Wk,
    const float* __restrict__ Wv)
{
    __shared__ __half th[32][40];
    const int mat = blockIdx.z;
    const float* __restrict__ W = (mat == 0) ? Wq : ((mat == 1) ? Wk : Wv);
    const int tid = threadIdx.x;
    const int k0 = blockIdx.x * 32;
    const int n0 = blockIdx.y * 32;
    {
        int r = tid >> 3, c4 = (tid & 7) * 4;
        float4 v = *(const float4*)(W + (size_t)(k0 + r) * D_MODEL + n0 + c4);
        H2U a, b;
        a.h2 = __floats2half2_rn(v.x, v.y);
        b.h2 = __floats2half2_rn(v.z, v.w);
        *(uint2*)&th[r][c4] = make_uint2(a.u, b.u);
    }
    __syncthreads();
    {
        int r = tid >> 3, c4 = (tid & 7) * 4;
        __half hh[4];
        #pragma unroll
        for (int j = 0; j < 4; ++j) hh[j] = th[c4 + j][r];
        size_t o = ((size_t)mat << 20) + (size_t)(n0 + r) * D_MODEL + k0 + c4;
        *(uint2*)(g_Wh + o) = *(uint2*)hh;
    }
}

// ===========================================================================
// QKV GEMM: fp16 HMMA 2-pass ((Dh+Dl)·Wh), 128x128 tile, BK=32, dbl-buffer.
// Q output pre-scaled by 0.125 (softmax scale folded in).
// ===========================================================================
#define ASTR 40
#define QT_BYTES (128 * ASTR * 2)      // 10240 per tile
#define QBUF_BYTES (3 * QT_BYTES)      // AH, AL, BH
#define QKV_SMEM (2 * QBUF_BYTES)      // 61440

__global__ __launch_bounds__(256, 2) void qkv_mma_kernel(
    const float* __restrict__ temporal,
    const float* __restrict__ bq, const float* __restrict__ bk,
    const float* __restrict__ bv)
{
    extern __shared__ char qsm[];
    const uint32_t base = smem_u32(qsm);

    const int mat = blockIdx.z;
    const float* __restrict__ bias = (mat == 0) ? bq : ((mat == 1) ? bk : bv);
    __half* __restrict__ outH = (mat == 0) ? g_Qh : ((mat == 1) ? g_Kh : g_Vh);
    const __half* __restrict__ Wh = g_Wh + ((size_t)mat << 20);

    const int tid = threadIdx.x;
    const int lane = tid & 31;
    const int wid = tid >> 5;
    const int wm = wid & 1;
    const int wn = wid >> 1;
    const int m0 = blockIdx.x * 128;
    const int n0 = blockIdx.y * 128;

    const int lrow = tid >> 2;
    const int lc8  = (tid & 3) * 8;

    auto prefetch = [&](int kk, int buf) {
        uint32_t bb = base + buf * QBUF_BYTES;
        #pragma unroll
        for (int it = 0; it < 2; ++it) {
            int row = lrow + it * 64;
            uint32_t so = (uint32_t)(row * ASTR + lc8) * 2;
            size_t ga = (size_t)(m0 + row) * D_MODEL + kk + lc8;
            size_t gb = (size_t)(n0 + row) * D_MODEL + kk + lc8;
            cp16(bb + so,                 g_Dh + ga);
            cp16(bb + QT_BYTES + so,      g_Dl + ga);
            cp16(bb + 2 * QT_BYTES + so,  Wh + gb);
        }
    };

    float acc[4][4][4];
    #pragma unroll
    for (int i = 0; i < 4; ++i)
        #pragma unroll
        for (int j = 0; j < 4; ++j)
            #pragma unroll
            for (int e = 0; e < 4; ++e) acc[i][j][e] = 0.0f;

    prefetch(0, 0);
    CP_COMMIT();

    for (int c = 0; c < 32; ++c) {
        __syncthreads();
        if (c + 1 < 32) {
            prefetch((c + 1) * 32, (c + 1) & 1);
            CP_COMMIT();
            CP_WAIT1();
        } else {
            CP_WAIT0();
        }
        __syncthreads();

        const uint32_t bb = base + (c & 1) * QBUF_BYTES;
        const uint32_t bAh = bb;
        const uint32_t bAl = bb + QT_BYTES;
        const uint32_t bBh = bb + 2 * QT_BYTES;

        #pragma unroll
        for (int ks = 0; ks < 2; ++ks) {
            const int ko = ks * 16;
            uint32_t Ah[4][4], Al[4][4], Bh[2][4];
            const uint32_t aoff = (uint32_t)((wm * 64 + (lane & 15)) * ASTR
                                             + ko + ((lane >> 4) << 3)) * 2;
            #pragma unroll
            for (int ma = 0; ma < 4; ++ma) {
                ldsm_x4(Ah[ma], bAh + aoff + ma * 16 * ASTR * 2);
                ldsm_x4(Al[ma], bAl + aoff + ma * 16 * ASTR * 2);
            }
            {
                const int m = lane >> 3;
                #pragma unroll
                for (int nbp = 0; nbp < 2; ++nbp) {
                    int rr = wn * 32 + nbp * 16 + ((m >> 1) << 3) + (lane & 7);
                    int cc = ko + ((m & 1) << 3);
                    uint32_t off = (uint32_t)(rr * ASTR + cc) * 2;
                    ldsm_x4(Bh[nbp], bBh + off);
                }
            }
            #pragma unroll
            for (int ma = 0; ma < 4; ++ma)
                #pragma unroll
                for (int nbp = 0; nbp < 2; ++nbp) {
                    mma16816(acc[ma][2*nbp+0], Ah[ma], Bh[nbp] + 0);
                    mma16816(acc[ma][2*nbp+1], Ah[ma], Bh[nbp] + 2);
                }
            #pragma unroll
            for (int ma = 0; ma < 4; ++ma)
                #pragma unroll
                for (int nbp = 0; nbp < 2; ++nbp) {
                    mma16816(acc[ma][2*nbp+0], Al[ma], Bh[nbp] + 0);
                    mma16816(acc[ma][2*nbp+1], Al[ma], Bh[nbp] + 2);
                }
        }
    }

    // Epilogue: bias + RoPE; Q additionally scaled by 0.125.
    #pragma unroll
    for (int ma = 0; ma < 4; ++ma) {
        const int r0 = m0 + wm * 64 + ma * 16 + (lane >> 2);
        #pragma unroll
        for (int rg = 0; rg < 2; ++rg) {
            const int r = r0 + rg * 8;
            const int bb = r >> 11;
            const int ll = r & (SEQ - 1);
            float t = 0.0f;
            if (mat < 2) t = temporal[r];
            #pragma unroll
            for (int nb = 0; nb < 4; ++nb) {
                const int n = n0 + wn * 32 + nb * 8 + (lane & 3) * 2;
                const int hh = n >> 6;
                const int s = n & 63;
                float x0 = acc[ma][nb][rg * 2 + 0] + bias[n];
                float x1 = acc[ma][nb][rg * 2 + 1] + bias[n + 1];
                float2 v;
                if (mat < 2) {
                    float f = exp2f(-(float)s * (LOG2_10K / (float)HEAD_DIM));
                    float sn, cs;
                    sincosf(t * f, &sn, &cs);
                    v.x = x0 * cs - x1 * sn;
                    v.y = x1 * cs + x0 * sn;
                } else {
                    v.x = x0; v.y = x1;
                }
                if (mat == 0) { v.x *= 0.125f; v.y *= 0.125f; }
                unsigned uh = packhf(v.x, v.y);
                size_t o = (((size_t)(bb * NHEAD + hh)) * SEQ + ll) * HEAD_DIM + s;
                *(unsigned*)(outH + o) = uh;
            }
        }
    }
}

// ===========================================================================
// Flash attention: fp16 HMMA SINGLE-pass. Q block 64 (pre-scaled), K/V fp16,
// KV tile 64 double-buffered, mask inline, 4 CTAs/SM.
// S = Qh·Kh ; O += Ph·Vh
// ===========================================================================
#define FSTR 72
#define HT_BYTES (64 * FSTR * 2)           // 9216 per 64-row fp16 tile
#define KVBUF_BYTES (2 * HT_BYTES)         // KH, VH = 18432
#define O_QH 0
#define O_KV HT_BYTES
#define AT_SMEM (HT_BYTES + 2 * KVBUF_BYTES)   // 46080

__global__ __launch_bounds__(128, 4) void attn_mma_kernel(
    const float* __restrict__ mask, float* __restrict__ out)
{
    extern __shared__ char smc[];
    const uint32_t base = smem_u32(smc);

    const int tid = threadIdx.x;
    const int lane = tid & 31;
    const int wid = tid >> 5;          // 0..3
    const int q0 = blockIdx.x * 64;
    const int hh = blockIdx.y;
    const int bb = blockIdx.z;

    const size_t hb = ((size_t)(bb * NHEAD + hh)) * SEQ * HEAD_DIM;

    // Q prefetch: 64 rows x 64 cols
    {
        #pragma unroll
        for (int it = 0; it < 4; ++it) {
            int idx = tid + it * 128;
            int row = idx >> 3;
            int c8  = (idx & 7) * 8;
            uint32_t so = (uint32_t)(row * FSTR + c8) * 2;
            size_t g = hb + (size_t)(q0 + row) * HEAD_DIM + c8;
            cp16(base + O_QH + so, g_Qh + g);
        }
    }

    auto prefetch_kv = [&](int c, int buf) {
        uint32_t bbse = base + O_KV + buf * KVBUF_BYTES;
        #pragma unroll
        for (int it = 0; it < 4; ++it) {
            int idx = tid + it * 128;
            int row = idx >> 3;
            int c8  = (idx & 7) * 8;
            uint32_t so = (uint32_t)(row * FSTR + c8) * 2;
            size_t g = hb + (size_t)(c * 64 + row) * HEAD_DIM + c8;
            cp16(bbse + so,            g_Kh + g);
            cp16(bbse + HT_BYTES + so, g_Vh + g);
        }
    };
    prefetch_kv(0, 0);
    CP_COMMIT();

    float O[8][4];
    #pragma unroll
    for (int i = 0; i < 8; ++i)
        #pragma unroll
        for (int e = 0; e < 4; ++e) O[i][e] = 0.0f;
    float mrow[2] = {-INFINITY, -INFINITY};
    float lrow_[2] = {0.0f, 0.0f};

    const int r0 = lane >> 2;
    const int qr0 = q0 + wid * 16 + r0;
    const int cq = (lane & 3) * 2;
    const int m = lane >> 3;

    const int NIT = SEQ / 64;
    for (int c = 0; c < NIT; ++c) {
        __syncthreads();
        if (c + 1 < NIT) {
            prefetch_kv(c + 1, (c + 1) & 1);
            CP_COMMIT();
            CP_WAIT1();
        } else {
            CP_WAIT0();
        }
        __syncthreads();

        const uint32_t bufb = base + O_KV + (c & 1) * KVBUF_BYTES;
        const uint32_t bKH = bufb;
        const uint32_t bVH = bufb + HT_BYTES;
        const int k0 = c * 64;

        // --- S = Qh.Kh^T (1-pass), warp strip m16 x n64 ---
        float acc[8][4];
        #pragma unroll
        for (int i = 0; i < 8; ++i)
            #pragma unroll
            for (int e = 0; e < 4; ++e) acc[i][e] = 0.0f;

        #pragma unroll
        for (int ks = 0; ks < 4; ++ks) {
            uint32_t Ah[4];
            const uint32_t aoff = (uint32_t)((wid * 16 + (lane & 15)) * FSTR
                                             + ks * 16 + ((lane >> 4) << 3)) * 2;
            ldsm_x4(Ah, base + O_QH + aoff);
            uint32_t Bh[4][4];
            #pragma unroll
            for (int nbp = 0; nbp < 4; ++nbp) {
                int rr = nbp * 16 + ((m >> 1) << 3) + (lane & 7);
                int cc = ks * 16 + ((m & 1) << 3);
                uint32_t off = (uint32_t)(rr * FSTR + cc) * 2;
                ldsm_x4(Bh[nbp], bKH + off);
            }
            #pragma unroll
            for (int nbp = 0; nbp < 4; ++nbp) {
                mma16816(acc[2*nbp+0], Ah, Bh[nbp] + 0);
                mma16816(acc[2*nbp+1], Ah, Bh[nbp] + 2);
            }
        }

        // --- online softmax (warp-local, quad shuffles), mask inline ---
        #pragma unroll
        for (int rg = 0; rg < 2; ++rg) {
            const float* mp = mask + (size_t)(qr0 + rg * 8) * SEQ + k0;
            float tm = -INFINITY;
            #pragma unroll
            for (int nb = 0; nb < 8; ++nb) {
                float2 mv = *(const float2*)(mp + nb * 8 + cq);
                float x0 = acc[nb][rg * 2 + 0] + mv.x;
                float x1 = acc[nb][rg * 2 + 1] + mv.y;
                acc[nb][rg * 2 + 0] = x0;
                acc[nb][rg * 2 + 1] = x1;
                tm = fmaxf(tm, fmaxf(x0, x1));
            }
            tm = fmaxf(tm, __shfl_xor_sync(0xffffffffu, tm, 1));
            tm = fmaxf(tm, __shfl_xor_sync(0xffffffffu, tm, 2));
            float mn = fmaxf(mrow[rg], tm);
            float corr = __expf(mrow[rg] - mn);
            float rs = 0.0f;
            #pragma unroll
            for (int nb = 0; nb < 8; ++nb) {
                float p0 = __expf(acc[nb][rg * 2 + 0] - mn);
                float p1 = __expf(acc[nb][rg * 2 + 1] - mn);
                acc[nb][rg * 2 + 0] = p0;
                acc[nb][rg * 2 + 1] = p1;
                rs += p0 + p1;
            }
            rs += __shfl_xor_sync(0xffffffffu, rs, 1);
            rs += __shfl_xor_sync(0xffffffffu, rs, 2);
            lrow_[rg] = lrow_[rg] * corr + rs;
            mrow[rg] = mn;
            #pragma unroll
            for (int nb = 0; nb < 8; ++nb) {
                O[nb][rg * 2 + 0] *= corr;
                O[nb][rg * 2 + 1] *= corr;
            }
        }

        // --- O += Ph.Vh (1-pass), P packed from registers ---
        #pragma unroll
        for (int ks = 0; ks < 4; ++ks) {
            uint32_t ph[4];
            #pragma unroll
            for (int half = 0; half < 2; ++half) {
                const float* a0 = acc[2 * ks + half];
                ph[half * 2 + 0] = packhf(a0[0], a0[1]);
                ph[half * 2 + 1] = packhf(a0[2], a0[3]);
            }
            uint32_t Vh[4][4];
            #pragma unroll
            for (int nbp = 0; nbp < 4; ++nbp) {
                int rr = ks * 16 + ((m & 1) << 3) + (lane & 7);
                int cc = nbp * 16 + ((m >> 1) << 3);
                uint32_t off = (uint32_t)(rr * FSTR + cc) * 2;
                ldsm_x4t(Vh[nbp], bVH + off);
            }
            #pragma unroll
            for (int nbp = 0; nbp < 4; ++nbp) {
                mma16816(O[2*nbp+0], ph, Vh[nbp] + 0);
                mma16816(O[2*nbp+1], ph, Vh[nbp] + 2);
            }
        }
    }

    // Epilogue
    float inv0 = 1.0f / lrow_[0];
    float inv1 = 1.0f / lrow_[1];
    #pragma unroll
    for (int rg = 0; rg < 2; ++rg) {
        float inv = rg ? inv1 : inv0;
        size_t ob = (size_t)(bb * SEQ + qr0 + rg * 8) * D_MODEL + hh * HEAD_DIM;
        #pragma unroll
        for (int nb = 0; nb < 8; ++nb) {
            float2 v = make_float2(O[nb][rg * 2 + 0] * inv, O[nb][rg * 2 + 1] * inv);
            *(float2*)(out + ob + nb * 8 + cq) = v;
        }
    }
}

// ---------------------------------------------------------------------------
// Launch. inputs: 0=data 1=temporal 2=mask 3=Wq 4=bq 5=Wk 6=bk 7=Wv 8=bv
// ---------------------------------------------------------------------------
extern "C" void kernel_launch(void* const* d_in, const int* in_sizes, int n_in,
                              void* d_out, int out_size)
{
    const float* data     = (const float*)d_in[0];
    const float* temporal = (const float*)d_in[1];
    const float* mask     = (const float*)d_in[2];
    const float* Wq = (const float*)d_in[3];
    const float* bq = (const float*)d_in[4];
    const float* Wk = (const float*)d_in[5];
    const float* bk = (const float*)d_in[6];
    const float* Wv = (const float*)d_in[7];
    const float* bv = (const float*)d_in[8];
    float* out = (float*)d_out;

    cudaFuncSetAttribute(qkv_mma_kernel,
                         cudaFuncAttributeMaxDynamicSharedMemorySize, QKV_SMEM);
    cudaFuncSetAttribute(attn_mma_kernel,
                         cudaFuncAttributeMaxDynamicSharedMemorySize, AT_SMEM);

    dsplit_kernel<<<(M_TOT * D_MODEL / 4) / 256, 256>>>(data);
    dim3 gw(D_MODEL / 32, D_MODEL / 32, 3);
    wsplit_kernel<<<gw, 256>>>(Wq, Wk, Wv);

    dim3 g1(M_TOT / 128, D_MODEL / 128, 3);
    qkv_mma_kernel<<<g1, 256, QKV_SMEM>>>(temporal, bq, bk, bv);

    dim3 g2(SEQ / 64, NHEAD, BATCH);
    attn_mma_kernel<<<g2, 128, AT_SMEM>>>(mask, out);
}